// round 15
// baseline (speedup 1.0000x reference)
#include <cuda_runtime.h>
#include <cstddef>

#define NUM_CLASSES 1000000
#define FEAT_DIM    128
#define BATCH       16384
#define ALPHA       0.5f

#define N_ELEMS   ((size_t)NUM_CLASSES * FEAT_DIM)   // 128,000,000
#define N_QUADS   (N_ELEMS / 4)                       // 32,000,000
#define N_PAIRS   (N_QUADS / 2)                       // 16,000,000 (2 quads/thread)

// 7/8-ish split, both segments divisible by 256 threads/block.
#define P_A       14080000                            // pairs in copy_A (55000 blocks)
#define P_B       (N_PAIRS - P_A)                     // 1,920,000 pairs (7500 blocks)
// copy_A writes out elems [1 .. 8*P_A]; row l complete iff 128l+128 <= 8*P_A
#define L_SPLIT   880000                              // update_lo: l < L_SPLIT

#define HI_MAX_WARPS 4096                             // list capacity (expected ~2032)

// Scratch. .bss => zero-initialized at load; clean-on-exit in the update
// kernels + k_clear restores zeroed state for the next graph replay.
__device__ float  g_sums[N_ELEMS];      // 512 MB static bss
__device__ float  g_counts[NUM_CLASSES];
__device__ int    g_owner[BATCH];       // 1 if batch elem is unique owner of its label
__device__ int    g_hi_list[BATCH];     // batch indices of hi-label owners
__device__ int    g_hi_count;
__device__ double g_loss;

// ---------------------------------------------------------------------------
// K0 (side stream head, 1 thread, hidden under copy_A ramp): reset the
// hi-owner list counter before k_accum pushes into it.
// ---------------------------------------------------------------------------
__global__ void k_clear() { g_hi_count = 0; }

// ---------------------------------------------------------------------------
// K1 (side stream, hidden under copy_A): scatter features into per-class
// sums + counts, accumulate loss (block reduction -> 1 double atomic/block),
// elect one owner warp per distinct label, and push hi-label owners into a
// compact list for the list-driven update_hi.
// One warp per batch element; lane k owns feature quad k.
// ---------------------------------------------------------------------------
__global__ void k_accum(const float* __restrict__ features,
                        const float* __restrict__ centers,
                        const int*   __restrict__ labels)
{
    const int gid  = blockIdx.x * blockDim.x + threadIdx.x;
    const int w    = gid >> 5;
    const int lane = gid & 31;
    const int wib  = threadIdx.x >> 5;

    __shared__ float s_part[8];

    float v = 0.0f;
    if (w < BATCH) {
        const int l = labels[w];
        const float4 f = reinterpret_cast<const float4*>(features)[(size_t)w * 32 + lane];
        const float4 c = reinterpret_cast<const float4*>(centers )[(size_t)l * 32 + lane];

        float* srow = g_sums + (size_t)l * FEAT_DIM + lane * 4;
        atomicAdd(srow + 0, f.x);
        atomicAdd(srow + 1, f.y);
        atomicAdd(srow + 2, f.z);
        atomicAdd(srow + 3, f.w);
        if (lane == 0) {
            const float old = atomicAdd(&g_counts[l], 1.0f);
            if (old == 0.0f) {
                g_owner[w] = 1;
                if (l >= L_SPLIT) {
                    const int pos = atomicAdd(&g_hi_count, 1);
                    g_hi_list[pos] = w;
                }
            } else {
                g_owner[w] = 0;
            }
        }

        const float dx = f.x - c.x, dy = f.y - c.y, dz = f.z - c.z, dw = f.w - c.w;
        v = dx * dx + dy * dy + dz * dz + dw * dw;
    }

    #pragma unroll
    for (int o = 16; o > 0; o >>= 1)
        v += __shfl_down_sync(0xffffffffu, v, o);
    if (lane == 0) s_part[wib] = v;
    __syncthreads();
    if (threadIdx.x == 0) {
        float tot = 0.0f;
        #pragma unroll
        for (int i = 0; i < 8; i++) tot += s_part[i];
        atomicAdd(&g_loss, (double)tot);
    }
}

// ---------------------------------------------------------------------------
// K2: PURE bulk shifted copy (R11 winner: 2 sequential quads / thread),
// over pair range starting at base. Thread p owns src quads 2p, 2p+1:
//   dst[2p]   = { c[8p-1], b0.xyz }   (straddle from prev thread / shfl)
//   dst[2p+1] = { b0.w, b1.xyz }      (straddle is local — free)
// Evict-first hints: the 1 GB stream is touch-once.
// p==0 (first segment only) writes head out[1..3] and tail out[N].
// ---------------------------------------------------------------------------
__global__ void k_copy(const float* __restrict__ c, float* __restrict__ out,
                       size_t base)
{
    const size_t p  = base + (size_t)blockIdx.x * blockDim.x + threadIdx.x;
    const float4 b0 = __ldcs(reinterpret_cast<const float4*>(c) + 2 * p);
    const float4 b1 = __ldcs(reinterpret_cast<const float4*>(c) + 2 * p + 1);

    float pw = __shfl_up_sync(0xffffffffu, b1.w, 1);   // prev thread's last elem
    if ((threadIdx.x & 31) == 0 && p > 0)
        pw = __ldg(c + 8 * p - 1);

    if (p == 0) {
        out[1] = b0.x; out[2] = b0.y; out[3] = b0.z;
        out[N_ELEMS] = c[N_ELEMS - 1];                 // tail element
    } else {
        __stcs(reinterpret_cast<float4*>(out) + 2 * p,
               make_float4(pw, b0.x, b0.y, b0.z));
    }
    __stcs(reinterpret_cast<float4*>(out) + 2 * p + 1,
           make_float4(b0.w, b1.x, b1.y, b1.z));
}

// ---------------------------------------------------------------------------
// Shared row-update body: momentum update with dst-aligned float4 stores
// (lane k stores out quad 32l+k = {val[4k-1] via shfl, val[4k..4k+2]}), then
// clean-on-exit clears of the scratch consumed.
// ---------------------------------------------------------------------------
__device__ __forceinline__ void update_row(const float* __restrict__ centers,
                                           float* __restrict__ out,
                                           int l, int w, int lane)
{
    const float cnt = g_counts[l];
    const float k1  = 1.0f - ALPHA;
    const float k2  = ALPHA / fmaxf(cnt, 1.0f);

    const size_t q = (size_t)l * 32 + lane;
    const float4 c = reinterpret_cast<const float4*>(centers)[q];
    const float4 s = reinterpret_cast<const float4*>(g_sums)[q];

    float4 val;
    val.x = k1 * c.x + k2 * s.x;
    val.y = k1 * c.y + k2 * s.y;
    val.z = k1 * c.z + k2 * s.z;
    val.w = k1 * c.w + k2 * s.w;

    const float pw = __shfl_up_sync(0xffffffffu, val.w, 1);  // val[4k-1]

    const size_t row = 1 + (size_t)l * FEAT_DIM;
    if (lane == 0) {
        out[row + 0] = val.x;
        out[row + 1] = val.y;
        out[row + 2] = val.z;
    } else {
        reinterpret_cast<float4*>(out)[q] =
            make_float4(pw, val.x, val.y, val.z);
    }
    if (lane == 31)
        out[row + 127] = val.w;

    // clean-on-exit for the next replay
    reinterpret_cast<float4*>(g_sums)[q] = make_float4(0.f, 0.f, 0.f, 0.f);
    if (lane == 0) {
        g_counts[l] = 0.0f;
        g_owner[w]  = 0;
    }
}

// ---------------------------------------------------------------------------
// K3 (side stream, hidden under copy_B): full-scan update of owner rows with
// label < L_SPLIT (finished by copy_A). Thread 0 emits loss + resets accum.
// ---------------------------------------------------------------------------
__global__ void k_update_lo(const float* __restrict__ centers,
                            const int*   __restrict__ labels,
                            float*       __restrict__ out)
{
    const int gid  = blockIdx.x * blockDim.x + threadIdx.x;
    const int w    = gid >> 5;
    const int lane = gid & 31;

    if (gid == 0) {
        out[0] = (float)(g_loss / (2.0 * (double)BATCH));
        g_loss = 0.0;
    }
    if (w >= BATCH) return;
    if (!g_owner[w]) return;                 // warp-uniform
    const int l = labels[w];
    if (l >= L_SPLIT) return;                // warp-uniform

    update_row(centers, out, l, w, lane);
}

// ---------------------------------------------------------------------------
// K4 (main stream, the only exposed update work): list-driven update of
// hi-label owner rows. Warp i processes g_hi_list[i]; no batch scan.
// ---------------------------------------------------------------------------
__global__ void k_update_hi(const float* __restrict__ centers,
                            const int*   __restrict__ labels,
                            float*       __restrict__ out)
{
    const int gid  = blockIdx.x * blockDim.x + threadIdx.x;
    const int i    = gid >> 5;
    const int lane = gid & 31;

    if (i >= g_hi_count) return;             // warp-uniform (count stable here)
    const int w = g_hi_list[i];
    const int l = labels[w];

    update_row(centers, out, l, w, lane);
}

// ---------------------------------------------------------------------------
// Pipelined topology, 7/8 + 1/8 split:
//   main:  copy_A --------------------> copy_B -> (wait accum) update_hi -> join
//   side:  clear -> accum -> [eAcc] -> (wait copy_A) update_lo(+loss) -> [eSide]
// update_lo (87.5% of rows) hides under copy_B; update_hi is list-driven
// (512 blocks, ~254 active) and the only exposed update. All capture-safe.
// ---------------------------------------------------------------------------
extern "C" void kernel_launch(void* const* d_in, const int* in_sizes, int n_in,
                              void* d_out, int out_size)
{
    const float* features = (const float*)d_in[0];
    const float* centers  = (const float*)d_in[1];
    const int*   labels   = (const int*)d_in[2];
    float*       out      = (float*)d_out;

    (void)in_sizes; (void)n_in; (void)out_size;

    const int warps_grid = (BATCH * 32) / 256;          // 2048 blocks of 256
    const int hi_blocks  = (HI_MAX_WARPS * 32) / 256;   // 512 blocks

    int prLo = 0, prHi = 0;
    cudaDeviceGetStreamPriorityRange(&prLo, &prHi);

    cudaStream_t s2;
    cudaEvent_t  eFork, eAcc, eCopyA, eSide;
    cudaStreamCreateWithPriority(&s2, cudaStreamNonBlocking, prHi);
    cudaEventCreateWithFlags(&eFork,  cudaEventDisableTiming);
    cudaEventCreateWithFlags(&eAcc,   cudaEventDisableTiming);
    cudaEventCreateWithFlags(&eCopyA, cudaEventDisableTiming);
    cudaEventCreateWithFlags(&eSide,  cudaEventDisableTiming);

    // fork side stream into the capture
    cudaEventRecord(eFork, 0);
    cudaStreamWaitEvent(s2, eFork, 0);

    // side: reset list counter, then accumulate (hidden under copy_A)
    k_clear<<<1, 1, 0, s2>>>();
    k_accum<<<warps_grid, 256, 0, s2>>>(features, centers, labels);
    cudaEventRecord(eAcc, s2);

    // main: bulk copy, segment A (7/8)
    k_copy<<<P_A / 256, 256>>>(centers, out, 0);
    cudaEventRecord(eCopyA, 0);

    // main: bulk copy, segment B (1/8)
    k_copy<<<P_B / 256, 256>>>(centers, out, (size_t)P_A);

    // side: update rows finished by copy_A (hidden under copy_B), emit loss
    cudaStreamWaitEvent(s2, eCopyA, 0);
    k_update_lo<<<warps_grid, 256, 0, s2>>>(centers, labels, out);
    cudaEventRecord(eSide, s2);

    // main: list-driven hi-label update (needs accum + copy_B); join side
    cudaStreamWaitEvent(0, eAcc, 0);
    k_update_hi<<<hi_blocks, 256>>>(centers, labels, out);
    cudaStreamWaitEvent(0, eSide, 0);

    cudaEventDestroy(eFork);
    cudaEventDestroy(eAcc);
    cudaEventDestroy(eCopyA);
    cudaEventDestroy(eSide);
    cudaStreamDestroy(s2);
}

// round 16
// speedup vs baseline: 1.0097x; 1.0097x over previous
#include <cuda_runtime.h>
#include <cstddef>

#define NUM_CLASSES 1000000
#define FEAT_DIM    128
#define BATCH       16384
#define ALPHA       0.5f

#define N_ELEMS   ((size_t)NUM_CLASSES * FEAT_DIM)   // 128,000,000
#define N_QUADS   (N_ELEMS / 4)                       // 32,000,000
#define N_PAIRS   (N_QUADS / 2)                       // 16,000,000 (2 quads/thread)

// 15/16-ish split, both segments divisible by 512 threads/block.
#define P_A       15000064                            // pairs in copy_A (29297 blocks @512)
#define P_B       (N_PAIRS - P_A)                     // 999,936 pairs (1953 blocks @512)
// copy_A writes out elems [1 .. 8*P_A]; row l complete iff 128l+128 <= 8*P_A
#define L_SPLIT   937504                              // update_lo: l < L_SPLIT

// Scratch. .bss => zero-initialized at load; clean-on-exit in k_update
// restores zeroed state for the next graph replay.
__device__ float  g_sums[N_ELEMS];      // 512 MB static bss
__device__ float  g_counts[NUM_CLASSES];
__device__ int    g_owner[BATCH];       // 1 if batch elem is unique owner of its label
__device__ double g_loss;

// ---------------------------------------------------------------------------
// K1 (side stream, hidden under copy_A): scatter features into per-class
// sums + counts, accumulate loss (block reduction -> 1 double atomic/block),
// elect one owner warp per distinct label.
// One warp per batch element; lane k owns feature quad k.
// ---------------------------------------------------------------------------
__global__ void k_accum(const float* __restrict__ features,
                        const float* __restrict__ centers,
                        const int*   __restrict__ labels)
{
    const int gid  = blockIdx.x * blockDim.x + threadIdx.x;
    const int w    = gid >> 5;
    const int lane = gid & 31;
    const int wib  = threadIdx.x >> 5;

    __shared__ float s_part[8];

    float v = 0.0f;
    if (w < BATCH) {
        const int l = labels[w];
        const float4 f = reinterpret_cast<const float4*>(features)[(size_t)w * 32 + lane];
        const float4 c = reinterpret_cast<const float4*>(centers )[(size_t)l * 32 + lane];

        float* srow = g_sums + (size_t)l * FEAT_DIM + lane * 4;
        atomicAdd(srow + 0, f.x);
        atomicAdd(srow + 1, f.y);
        atomicAdd(srow + 2, f.z);
        atomicAdd(srow + 3, f.w);
        if (lane == 0) {
            const float old = atomicAdd(&g_counts[l], 1.0f);
            g_owner[w] = (old == 0.0f) ? 1 : 0;
        }

        const float dx = f.x - c.x, dy = f.y - c.y, dz = f.z - c.z, dw = f.w - c.w;
        v = dx * dx + dy * dy + dz * dz + dw * dw;
    }

    #pragma unroll
    for (int o = 16; o > 0; o >>= 1)
        v += __shfl_down_sync(0xffffffffu, v, o);
    if (lane == 0) s_part[wib] = v;
    __syncthreads();
    if (threadIdx.x == 0) {
        float tot = 0.0f;
        #pragma unroll
        for (int i = 0; i < 8; i++) tot += s_part[i];
        atomicAdd(&g_loss, (double)tot);
    }
}

// ---------------------------------------------------------------------------
// K2: PURE bulk shifted copy (R11 winner: 2 sequential quads / thread),
// over pair range starting at base. Thread p owns src quads 2p, 2p+1:
//   dst[2p]   = { c[8p-1], b0.xyz }   (straddle from prev thread / shfl)
//   dst[2p+1] = { b0.w, b1.xyz }      (straddle is local — free)
// Evict-first hints: the 1 GB stream is touch-once.
// p==0 (first segment only) writes head out[1..3] and tail out[N].
// ---------------------------------------------------------------------------
__global__ void k_copy(const float* __restrict__ c, float* __restrict__ out,
                       size_t base)
{
    const size_t p  = base + (size_t)blockIdx.x * blockDim.x + threadIdx.x;
    const float4 b0 = __ldcs(reinterpret_cast<const float4*>(c) + 2 * p);
    const float4 b1 = __ldcs(reinterpret_cast<const float4*>(c) + 2 * p + 1);

    float pw = __shfl_up_sync(0xffffffffu, b1.w, 1);   // prev thread's last elem
    if ((threadIdx.x & 31) == 0 && p > 0)
        pw = __ldg(c + 8 * p - 1);

    if (p == 0) {
        out[1] = b0.x; out[2] = b0.y; out[3] = b0.z;
        out[N_ELEMS] = c[N_ELEMS - 1];                 // tail element
    } else {
        __stcs(reinterpret_cast<float4*>(out) + 2 * p,
               make_float4(pw, b0.x, b0.y, b0.z));
    }
    __stcs(reinterpret_cast<float4*>(out) + 2 * p + 1,
           make_float4(b0.w, b1.x, b1.y, b1.z));
}

// ---------------------------------------------------------------------------
// K3: owner warps with label in [lo, hi) overwrite their class row with the
// momentum update using dst-ALIGNED float4 stores. Lane k computes val =
// elems 4k..4k+3, stores out quad (32l+k) = {val[4k-1] via shfl, val[4k..+2]}
// covering row elems 4k-1..4k+2. Lane 0 writes elems 0..2 scalar; lane 31
// writes elem 127 scalar. Coverage complete, disjoint from adjacent rows.
// Then CLEAR the scratch consumed (clean-on-exit for the next replay).
// emit_loss: thread 0 writes out[0] and resets the accumulator.
//   new_c = (1-ALPHA)*c + (ALPHA/cnt)*sum
// ---------------------------------------------------------------------------
__global__ void k_update(const float* __restrict__ centers,
                         const int*   __restrict__ labels,
                         float*       __restrict__ out,
                         int lo, int hi, int emit_loss)
{
    const int gid  = blockIdx.x * blockDim.x + threadIdx.x;
    const int w    = gid >> 5;
    const int lane = gid & 31;

    if (emit_loss && gid == 0) {
        out[0] = (float)(g_loss / (2.0 * (double)BATCH));
        g_loss = 0.0;
    }
    if (w >= BATCH) return;
    if (!g_owner[w]) return;                 // warp-uniform
    const int l = labels[w];
    if (l < lo || l >= hi) return;           // warp-uniform

    const float cnt = g_counts[l];
    const float k1  = 1.0f - ALPHA;
    const float k2  = ALPHA / fmaxf(cnt, 1.0f);

    const size_t q = (size_t)l * 32 + lane;
    const float4 c = reinterpret_cast<const float4*>(centers)[q];
    const float4 s = reinterpret_cast<const float4*>(g_sums)[q];

    float4 val;
    val.x = k1 * c.x + k2 * s.x;
    val.y = k1 * c.y + k2 * s.y;
    val.z = k1 * c.z + k2 * s.z;
    val.w = k1 * c.w + k2 * s.w;

    const float pw = __shfl_up_sync(0xffffffffu, val.w, 1);  // val[4k-1]

    const size_t row = 1 + (size_t)l * FEAT_DIM;             // out[] idx of elem 0
    if (lane == 0) {
        out[row + 0] = val.x;
        out[row + 1] = val.y;
        out[row + 2] = val.z;
    } else {
        reinterpret_cast<float4*>(out)[q] =
            make_float4(pw, val.x, val.y, val.z);
    }
    if (lane == 31)
        out[row + 127] = val.w;

    // clean-on-exit: restore zeroed scratch for the next replay
    reinterpret_cast<float4*>(g_sums)[q] = make_float4(0.f, 0.f, 0.f, 0.f);
    if (lane == 0) {
        g_counts[l] = 0.0f;
        g_owner[w]  = 0;
    }
}

// ---------------------------------------------------------------------------
// Pipelined topology, 15/16 + 1/16 split (R14 structure, retuned):
//   main:  copy_A(29297 blk) -> copy_B(1953 blk) -> (wait accum) update_hi -> join
//   side:  accum -> [eAcc] -> (wait copy_A) -> update_lo(+loss) -> [eSide]
// update_lo (93.75% of rows) hides under copy_B (~10 us); only update_hi
// (~6.25% of owner rows) is exposed. All capture-safe.
// ---------------------------------------------------------------------------
extern "C" void kernel_launch(void* const* d_in, const int* in_sizes, int n_in,
                              void* d_out, int out_size)
{
    const float* features = (const float*)d_in[0];
    const float* centers  = (const float*)d_in[1];
    const int*   labels   = (const int*)d_in[2];
    float*       out      = (float*)d_out;

    (void)in_sizes; (void)n_in; (void)out_size;

    const int warps_grid = (BATCH * 32) / 256;          // 2048 blocks of 256

    int prLo = 0, prHi = 0;
    cudaDeviceGetStreamPriorityRange(&prLo, &prHi);

    cudaStream_t s2;
    cudaEvent_t  eFork, eAcc, eCopyA, eSide;
    cudaStreamCreateWithPriority(&s2, cudaStreamNonBlocking, prHi);
    cudaEventCreateWithFlags(&eFork,  cudaEventDisableTiming);
    cudaEventCreateWithFlags(&eAcc,   cudaEventDisableTiming);
    cudaEventCreateWithFlags(&eCopyA, cudaEventDisableTiming);
    cudaEventCreateWithFlags(&eSide,  cudaEventDisableTiming);

    // fork side stream into the capture
    cudaEventRecord(eFork, 0);
    cudaStreamWaitEvent(s2, eFork, 0);

    // side: accumulate (hidden under copy_A)
    k_accum<<<warps_grid, 256, 0, s2>>>(features, centers, labels);
    cudaEventRecord(eAcc, s2);

    // main: bulk copy, segment A (15/16), 512-thread blocks
    k_copy<<<P_A / 512, 512>>>(centers, out, 0);
    cudaEventRecord(eCopyA, 0);

    // main: bulk copy, segment B (1/16)
    k_copy<<<P_B / 512, 512>>>(centers, out, (size_t)P_A);

    // side: update rows finished by copy_A (hidden under copy_B), emit loss
    cudaStreamWaitEvent(s2, eCopyA, 0);
    k_update<<<warps_grid, 256, 0, s2>>>(centers, labels, out,
                                         0, L_SPLIT, /*emit_loss=*/1);
    cudaEventRecord(eSide, s2);

    // main: remaining high-label rows (needs accum + copy_B); join side last
    cudaStreamWaitEvent(0, eAcc, 0);
    k_update<<<warps_grid, 256>>>(centers, labels, out,
                                  L_SPLIT, NUM_CLASSES, /*emit_loss=*/0);
    cudaStreamWaitEvent(0, eSide, 0);

    cudaEventDestroy(eFork);
    cudaEventDestroy(eAcc);
    cudaEventDestroy(eCopyA);
    cudaEventDestroy(eSide);
    cudaStreamDestroy(s2);
}